// round 17
// baseline (speedup 1.0000x reference)
#include <cuda_runtime.h>

#define BATCH 256
#define NPTS  4096
#define DYN_SMEM (2*(NPTS*16 + NPTS*4))
#define FULLM 0xffffffffu

// ---------- fast double helpers ----------
__device__ __forceinline__ double drecip(double x) {
  double y = (double)__fdividef(1.0f, (float)x);
  y = y * (2.0 - x * y);
  return y;
}
__device__ __forceinline__ double drsqrt(double x) {
  double y = (double)rsqrtf((float)x);
  y = y * (1.5 - 0.5 * x * y * y);
  return y;
}

__device__ __forceinline__ void inv3x3(const float* __restrict__ Km, float* __restrict__ out) {
  double a=Km[0], b=Km[1], c=Km[2], d=Km[3], e=Km[4], f=Km[5], g=Km[6], h=Km[7], i=Km[8];
  double det = a*(e*i - f*h) - b*(d*i - f*g) + c*(d*h - e*g);
  double inv = 1.0 / det;
  out[0]=(float)((e*i - f*h)*inv); out[1]=(float)((c*h - b*i)*inv); out[2]=(float)((b*f - c*e)*inv);
  out[3]=(float)((f*g - d*i)*inv); out[4]=(float)((a*i - c*g)*inv); out[5]=(float)((c*d - a*f)*inv);
  out[6]=(float)((d*h - e*g)*inv); out[7]=(float)((b*g - a*h)*inv); out[8]=(float)((a*e - b*d)*inv);
}

__device__ __forceinline__ int p2i(int a, int b) {
  int mn = a < b ? a : b, mx = a < b ? b : a;
  return mn*(5-mn)/2 + mx;
}

template<int P, int Q>
__device__ __forceinline__ void rot3f(float g[3][3], float Qm[3][3]) {
  constexpr int K2 = 3 - P - Q;
  float apq = g[P][Q];
  float app = g[P][P], aqq = g[Q][Q];
  if (fabsf(apq) <= 1e-12f * (fabsf(app) + fabsf(aqq))) return;
  float tau = __fdividef(aqq - app, 2.0f * apq);
  float tt = ((tau >= 0.0f) ? 1.0f : -1.0f) / (fabsf(tau) + sqrtf(1.0f + tau*tau));
  float c = rsqrtf(1.0f + tt*tt);
  float s = tt * c;
  float akp = g[K2][P], akq = g[K2][Q];
  float np = c*akp - s*akq, nq = s*akp + c*akq;
  g[K2][P] = np; g[P][K2] = np;
  g[K2][Q] = nq; g[Q][K2] = nq;
  g[P][P] = app - tt*apq;
  g[Q][Q] = aqq + tt*apq;
  g[P][Q] = 0.0f; g[Q][P] = 0.0f;
  #pragma unroll
  for (int r = 0; r < 3; r++) {
    float qp = Qm[r][P], qq = Qm[r][Q];
    Qm[r][P] = c*qp - s*qq;
    Qm[r][Q] = s*qp + c*qq;
  }
}

// ---------- fused kernel: one block per TWO batches, interleaved loops ----------
__global__ __launch_bounds__(256, 1) void k_fused(const float* __restrict__ kpts0,
                                                  const float* __restrict__ kpts1,
                                                  const float* __restrict__ conf,
                                                  const float* __restrict__ tscale,
                                                  const float* __restrict__ Kmat,
                                                  float* __restrict__ out) {
  const int tid = threadIdx.x;
  const int warp = tid >> 5, lane = tid & 31;

  extern __shared__ char dyn[];
  float4* sPv0 = (float4*)dyn;
  float4* sPv1 = (float4*)(dyn + NPTS*16);
  float*  sWv0 = (float*)(dyn + 2*NPTS*16);
  float*  sWv1 = (float*)(dyn + 2*NPTS*16 + NPTS*4);

  __shared__ float sKi[2][18];
  __shared__ float sred[8][36];
  __shared__ double sd[2][81];
  __shared__ float sT[2][36];
  __shared__ float sR1[2][9], st3[2][3];
  __shared__ float scs[2][4], sss[2][4];
  __shared__ double sDinv[2][9], sSigma[2], sxd[2][9];
  __shared__ float sUVf[2][18], sSgnF[2];
  __shared__ int sIpiv[2][9];
  __shared__ int sPerm[2][9];
  __shared__ int sAffine[2];

  // ---- phase 0: K inverses ----
  if (tid < 2) {
    int bb = blockIdx.x*2 + tid;
    float ki0[9], ki1[9];
    inv3x3(Kmat + bb*18, ki0);
    inv3x3(Kmat + bb*18 + 9, ki1);
    #pragma unroll
    for (int i=0;i<9;i++) { sKi[tid][i]=ki0[i]; sKi[tid][9+i]=ki1[i]; }
    sAffine[tid] = (ki0[6]==0.f && ki0[7]==0.f && ki0[8]==1.f &&
                    ki1[6]==0.f && ki1[7]==0.f && ki1[8]==1.f) ? 1 : 0;
  }
  __syncthreads();

  const int bbA = blockIdx.x*2;
  const int bbB = blockIdx.x*2 + 1;
  const float2* kp0A = (const float2*)(kpts0) + (size_t)bbA*NPTS;
  const float2* kp1A = (const float2*)(kpts1) + (size_t)bbA*NPTS;
  const float*  wvA  = conf + (size_t)bbA*NPTS;
  const float2* kp0B = (const float2*)(kpts0) + (size_t)bbB*NPTS;
  const float2* kp1B = (const float2*)(kpts1) + (size_t)bbB*NPTS;
  const float*  wvB  = conf + (size_t)bbB*NPTS;

  // ---- phase 1: BOTH batches interleaved in one loop ----
  {
    float KA0[9], KA1[9], KB0[9], KB1[9];
    #pragma unroll
    for (int i=0;i<9;i++){
      KA0[i]=sKi[0][i]; KA1[i]=sKi[0][9+i];
      KB0[i]=sKi[1][i]; KB1[i]=sKi[1][9+i];
    }
    float acc0[36], acc1[36];
    #pragma unroll
    for (int i=0;i<36;i++){ acc0[i]=0.f; acc1[i]=0.f; }

    // prefetch depth 2 per batch (12 loads in flight)
    float2 pA0[2], pA1[2], pB0[2], pB1[2];
    float  wA[2], wB[2];
    #pragma unroll
    for (int i=0;i<2;i++) {
      pA0[i] = kp0A[tid + i*256]; pA1[i] = kp1A[tid + i*256]; wA[i] = wvA[tid + i*256];
      pB0[i] = kp0B[tid + i*256]; pB1[i] = kp1B[tid + i*256]; wB[i] = wvB[tid + i*256];
    }
    #pragma unroll
    for (int k = 0; k < NPTS/256; k++) {
      const int sl = k & 1;
      float2 a0 = pA0[sl], a1 = pA1[sl]; float aw = wA[sl];
      float2 c0 = pB0[sl], c1 = pB1[sl]; float cw = wB[sl];
      if (k + 2 < NPTS/256) {
        pA0[sl] = kp0A[tid + (k+2)*256]; pA1[sl] = kp1A[tid + (k+2)*256]; wA[sl] = wvA[tid + (k+2)*256];
        pB0[sl] = kp0B[tid + (k+2)*256]; pB1[sl] = kp1B[tid + (k+2)*256]; wB[sl] = wvB[tid + (k+2)*256];
      }
      int n = tid + k*256;
      // batch A
      {
        float x00 = KA0[0]*a0.x + KA0[1]*a0.y + KA0[2];
        float x01 = KA0[3]*a0.x + KA0[4]*a0.y + KA0[5];
        float x02 = KA0[6]*a0.x + KA0[7]*a0.y + KA0[8];
        float x10 = KA1[0]*a1.x + KA1[1]*a1.y + KA1[2];
        float x11 = KA1[3]*a1.x + KA1[4]*a1.y + KA1[5];
        float x12 = KA1[6]*a1.x + KA1[7]*a1.y + KA1[8];
        sPv0[n] = make_float4(x00, x01, x10, x11);
        sWv0[n] = aw;
        float s0a[6] = {x00*x00, x00*x01, x00*x02, x01*x01, x01*x02, x02*x02};
        float s1a[6] = {x10*x10, x10*x11, x10*x12, x11*x11, x11*x12, x12*x12};
        float ws1[6];
        #pragma unroll
        for (int a=0;a<6;a++) ws1[a] = aw*s1a[a];
        #pragma unroll
        for (int a=0;a<6;a++)
          #pragma unroll
          for (int bq=0;bq<6;bq++)
            acc0[a*6+bq] = fmaf(ws1[a], s0a[bq], acc0[a*6+bq]);
      }
      // batch B
      {
        float x00 = KB0[0]*c0.x + KB0[1]*c0.y + KB0[2];
        float x01 = KB0[3]*c0.x + KB0[4]*c0.y + KB0[5];
        float x02 = KB0[6]*c0.x + KB0[7]*c0.y + KB0[8];
        float x10 = KB1[0]*c1.x + KB1[1]*c1.y + KB1[2];
        float x11 = KB1[3]*c1.x + KB1[4]*c1.y + KB1[5];
        float x12 = KB1[6]*c1.x + KB1[7]*c1.y + KB1[8];
        sPv1[n] = make_float4(x00, x01, x10, x11);
        sWv1[n] = cw;
        float s0a[6] = {x00*x00, x00*x01, x00*x02, x01*x01, x01*x02, x02*x02};
        float s1a[6] = {x10*x10, x10*x11, x10*x12, x11*x11, x11*x12, x12*x12};
        float ws1[6];
        #pragma unroll
        for (int a=0;a<6;a++) ws1[a] = cw*s1a[a];
        #pragma unroll
        for (int a=0;a<6;a++)
          #pragma unroll
          for (int bq=0;bq<6;bq++)
            acc1[a*6+bq] = fmaf(ws1[a], s0a[bq], acc1[a*6+bq]);
      }
    }
    // reductions (batch A then B, same tree as before)
    #pragma unroll
    for (int i=0;i<36;i++) {
      acc0[i] += __shfl_down_sync(FULLM, acc0[i], 16);
      acc0[i] += __shfl_down_sync(FULLM, acc0[i], 8);
      acc0[i] += __shfl_down_sync(FULLM, acc0[i], 4);
      acc0[i] += __shfl_down_sync(FULLM, acc0[i], 2);
      acc0[i] += __shfl_down_sync(FULLM, acc0[i], 1);
    }
    if (lane == 0) {
      #pragma unroll
      for (int i=0;i<36;i++) sred[warp][i] = acc0[i];
    }
    __syncthreads();
    if (tid < 36) {
      float v = 0.f;
      #pragma unroll
      for (int wp=0; wp<8; wp++) v += sred[wp][tid];
      sT[0][tid] = v;
    }
    __syncthreads();
    #pragma unroll
    for (int i=0;i<36;i++) {
      acc1[i] += __shfl_down_sync(FULLM, acc1[i], 16);
      acc1[i] += __shfl_down_sync(FULLM, acc1[i], 8);
      acc1[i] += __shfl_down_sync(FULLM, acc1[i], 4);
      acc1[i] += __shfl_down_sync(FULLM, acc1[i], 2);
      acc1[i] += __shfl_down_sync(FULLM, acc1[i], 1);
    }
    if (lane == 0) {
      #pragma unroll
      for (int i=0;i<36;i++) sred[warp][i] = acc1[i];
    }
    __syncthreads();
    if (tid < 36) {
      float v = 0.f;
      #pragma unroll
      for (int wp=0; wp<8; wp++) v += sred[wp][tid];
      sT[1][tid] = v;
    }
    __syncthreads();
  }

  // ---- phase 2: TWO concurrent eigensolves (warp 0 / warp 1) ----
  if (warp < 2) {
    const int s = warp;
    float* A = (float*)&sd[s][0];

    if (lane < 9) {
      const int i0 = lane / 3, j0 = lane % 3;
      #pragma unroll
      for (int j = 0; j < 9; j++)
        A[lane*9+j] = sT[s][p2i(i0, j/3)*6 + p2i(j0, j%3)];
    }
    __syncwarp();

    for (int sweep = 0; sweep < 3; sweep++) {
      for (int r = 0; r < 9; r++) {
        const int bye = (5 * ((2*r) % 9)) % 9;
        if (lane < 4) {
          int d = lane + 1;
          int a = (bye + d) % 9;
          int bq = (bye + 9 - d) % 9;
          int p = a < bq ? a : bq;
          int q = a < bq ? bq : a;
          float apq = A[p*9+q], app = A[p*9+p], aqq = A[q*9+q];
          float c = 1.0f, sv = 0.0f;
          if (fabsf(apq) > 6e-8f * (fabsf(app) + fabsf(aqq))) {
            float tau = __fdividef(aqq - app, 2.0f * apq);
            float t = ((tau >= 0.0f) ? 1.0f : -1.0f) / (fabsf(tau) + sqrtf(1.0f + tau*tau));
            c = rsqrtf(1.0f + t*t);
            sv = t * c;
          }
          scs[s][lane] = c; sss[s][lane] = sv;
        }
        __syncwarp();
        float cr[4], sr[4];
        int pr[4], qr[4];
        #pragma unroll
        for (int d = 0; d < 4; d++) {
          cr[d] = scs[s][d]; sr[d] = sss[s][d];
          int a = (bye + d + 1) % 9;
          int bq = (bye + 8 - d) % 9;
          pr[d] = a < bq ? a : bq;
          qr[d] = a < bq ? bq : a;
        }
        if (lane < 9) {
          #pragma unroll
          for (int d = 0; d < 4; d++) {
            int p = pr[d], q = qr[d];
            float vp = A[lane*9+p], vq = A[lane*9+q];
            A[lane*9+p] = cr[d]*vp - sr[d]*vq;
            A[lane*9+q] = sr[d]*vp + cr[d]*vq;
          }
        }
        __syncwarp();
        if (lane < 9) {
          #pragma unroll
          for (int d = 0; d < 4; d++) {
            int p = pr[d], q = qr[d];
            float vp = A[p*9+lane], vq = A[q*9+lane];
            A[p*9+lane] = cr[d]*vp - sr[d]*vq;
            A[q*9+lane] = sr[d]*vp + cr[d]*vq;
          }
        }
        __syncwarp();
      }
    }

    if (lane == 0) {
      float mv = A[0];
      #pragma unroll
      for (int k=1;k<9;k++) mv = fminf(mv, A[k*9+k]);
      sSigma[s] = (double)mv;
    }
    __syncwarp();
    double sigma = sSigma[s];

    double* D = &sd[s][0];
    if (lane < 9) {
      int i0 = lane/3, j0 = lane%3;
      #pragma unroll
      for (int j=0;j<9;j++)
        D[lane*9+j] = (double)sT[s][p2i(i0, j/3)*6 + p2i(j0, j%3)];
      D[lane*9+lane] -= sigma;
    }
    __syncwarp();

    for (int k=0;k<9;k++) {
      double av = (lane < 9 && lane >= k) ? fabs(D[lane*9+k]) : -1.0;
      int ai = lane;
      #pragma unroll
      for (int off=16; off; off>>=1) {
        double ov = __shfl_xor_sync(FULLM, av, off);
        int oi = __shfl_xor_sync(FULLM, ai, off);
        if (ov > av || (ov == av && oi < ai)) { av = ov; ai = oi; }
      }
      int p = ai;
      if (lane == 0) sIpiv[s][k] = p;
      if (p != k && lane < 9) {
        double t = D[k*9+lane]; D[k*9+lane] = D[p*9+lane]; D[p*9+lane] = t;
      }
      __syncwarp();
      double pv = D[k*9+k];
      if (fabs(pv) < 1e-30) pv = (pv >= 0.0) ? 1e-30 : -1e-30;
      double ipv = drecip(pv);
      if (lane == 0) sDinv[s][k] = ipv;
      if (lane > k && lane < 9) {
        double l = D[lane*9+k] * ipv;
        D[lane*9+k] = l;
        for (int j=k+1;j<9;j++) D[lane*9+j] -= l * D[k*9+j];
      }
      __syncwarp();
    }

    if (lane == 0) {
      int idx[9];
      #pragma unroll
      for (int i=0;i<9;i++) idx[i]=i;
      for (int k=0;k<9;k++){ int p=sIpiv[s][k]; int t=idx[k]; idx[k]=idx[p]; idx[p]=t; }
      #pragma unroll
      for (int i=0;i<9;i++) sPerm[s][i]=idx[i];
    }
    __syncwarp();

    double row[9]; double dinv_l = 1.0; int permL = 0;
    if (lane < 9) {
      #pragma unroll
      for (int j=0;j<9;j++) row[j] = D[lane*9+j];
      dinv_l = sDinv[s][lane];
      permL = sPerm[s][lane];
    }

    double rv = 1.0;
    for (int it=0; it<2; it++) {
      if (lane < 9) sxd[s][lane] = rv;
      __syncwarp();
      if (lane < 9) rv = sxd[s][permL];
      __syncwarp();
      #pragma unroll
      for (int j=0;j<8;j++) {
        double yj = __shfl_sync(FULLM, rv, j);
        if (lane > j && lane < 9) rv -= row[j]*yj;
      }
      #pragma unroll
      for (int j=8;j>=0;j--) {
        if (lane == j) rv *= dinv_l;
        double xj = __shfl_sync(FULLM, rv, j);
        if (lane < j) rv -= row[j]*xj;
      }
      double c2 = (lane < 9) ? rv*rv : 0.0;
      #pragma unroll
      for (int off=16; off; off>>=1) c2 += __shfl_xor_sync(FULLM, c2, off);
      rv *= drsqrt(c2);
    }
    if (lane < 9) sxd[s][lane] = rv;
    __syncwarp();

    if (lane == 0) {
      float e[9];
      #pragma unroll
      for (int k=0;k<9;k++) e[k] = (float)sxd[s][k];

      float G3[3][3];
      #pragma unroll
      for (int i=0;i<3;i++)
        #pragma unroll
        for (int j=0;j<3;j++)
          G3[i][j] = e[0+i]*e[0+j] + e[3+i]*e[3+j] + e[6+i]*e[6+j];

      float Qm[3][3] = {{1.f,0.f,0.f},{0.f,1.f,0.f},{0.f,0.f,1.f}};
      #pragma unroll
      for (int sw=0; sw<4; sw++) { rot3f<0,1>(G3,Qm); rot3f<0,2>(G3,Qm); rot3f<1,2>(G3,Qm); }

      float lam0=G3[0][0], lam1=G3[1][1], lam2=G3[2][2];
      int o0, o1, o2;
      if (lam0 >= lam1) {
        if (lam0 >= lam2) { o0=0; if (lam1>=lam2){o1=1;o2=2;} else {o1=2;o2=1;} }
        else              { o0=2; o1=0; o2=1; }
      } else {
        if (lam1 >= lam2) { o0=1; if (lam0>=lam2){o1=0;o2=2;} else {o1=2;o2=0;} }
        else              { o0=2; o1=1; o2=0; }
      }
      float v1[3] = {Qm[0][o0], Qm[1][o0], Qm[2][o0]};
      float v2[3] = {Qm[0][o1], Qm[1][o1], Qm[2][o1]};
      float v3[3] = {Qm[0][o2], Qm[1][o2], Qm[2][o2]};

      float u1[3], u2[3], u3[3];
      #pragma unroll
      for (int i=0;i<3;i++) {
        u1[i] = e[3*i+0]*v1[0] + e[3*i+1]*v1[1] + e[3*i+2]*v1[2];
        u2[i] = e[3*i+0]*v2[0] + e[3*i+1]*v2[1] + e[3*i+2]*v2[2];
      }
      float in1 = rsqrtf(fmaxf(u1[0]*u1[0]+u1[1]*u1[1]+u1[2]*u1[2], 1e-30f));
      float in2 = rsqrtf(fmaxf(u2[0]*u2[0]+u2[1]*u2[1]+u2[2]*u2[2], 1e-30f));
      #pragma unroll
      for (int i=0;i<3;i++){ u1[i]*=in1; u2[i]*=in2; }
      u3[0] = u1[1]*u2[2] - u1[2]*u2[1];
      u3[1] = u1[2]*u2[0] - u1[0]*u2[2];
      u3[2] = u1[0]*u2[1] - u1[1]*u2[0];
      float in3 = rsqrtf(fmaxf(u3[0]*u3[0]+u3[1]*u3[1]+u3[2]*u3[2], 1e-30f));
      #pragma unroll
      for (int i=0;i<3;i++) u3[i]*=in3;

      float detU = u1[0]*(u2[1]*u3[2]-u2[2]*u3[1])
                 - u1[1]*(u2[0]*u3[2]-u2[2]*u3[0])
                 + u1[2]*(u2[0]*u3[1]-u2[1]*u3[0]);
      float detV = v1[0]*(v2[1]*v3[2]-v2[2]*v3[1])
                 - v1[1]*(v2[0]*v3[2]-v2[2]*v3[0])
                 + v1[2]*(v2[0]*v3[1]-v2[1]*v3[0]);
      float dd = detU * detV;
      sSgnF[s] = (dd > 0.0f) ? 1.0f : ((dd < 0.0f) ? -1.0f : 0.0f);
      #pragma unroll
      for (int i=0;i<3;i++) {
        sUVf[s][i]    = u1[i];
        sUVf[s][3+i]  = u2[i];
        sUVf[s][6+i]  = u3[i];
        sUVf[s][9+i]  = v1[i];
        sUVf[s][12+i] = v2[i];
        sUVf[s][15+i] = v3[i];
        st3[s][i] = u3[i];
      }
    }
    __syncwarp();

    if (lane < 9) {
      int i = lane / 3, j = lane % 3;
      float u1i = sUVf[s][i], u2i = sUVf[s][3+i], u3i = sUVf[s][6+i];
      float v1j = sUVf[s][9+j], v2j = sUVf[s][12+j], v3j = sUVf[s][15+j];
      sR1[s][lane] = ( u2i*v1j - u1i*v2j + u3i*v3j)*sSgnF[s];
    }
  }
  __syncthreads();

  // ---- phase 3: cheirality, both batches interleaved (H-trick for candidate 2) ----
  float scA0=0.f, scA1=0.f, scA2=0.f, scA3=0.f;
  float scB0=0.f, scB1=0.f, scB2=0.f, scB3=0.f;
  {
    float RA[9], RB[9];
    #pragma unroll
    for (int i=0;i<9;i++){ RA[i]=sR1[0][i]; RB[i]=sR1[1][i]; }
    const float ta0=st3[0][0], ta1=st3[0][1], ta2=st3[0][2];
    const float tb0=st3[1][0], tb1=st3[1][1], tb2=st3[1][2];
    const bool bothAffine = sAffine[0] && sAffine[1];

    if (bothAffine) {
      #pragma unroll
      for (int k = 0; k < NPTS/256; k++) {
        int n = tid + k*256;
        float4 qa = sPv0[n]; float wa = sWv0[n];
        float4 qb = sPv1[n]; float wb = sWv1[n];
        // batch A
        {
          float bbv = qa.z*qa.z + qa.w*qa.w + 1.0f;
          float bt = qa.z*ta0 + qa.w*ta1 + ta2;
          float a0 = RA[0]*qa.x + RA[1]*qa.y + RA[2];
          float a1 = RA[3]*qa.x + RA[4]*qa.y + RA[5];
          float a2 = RA[6]*qa.x + RA[7]*qa.y + RA[8];
          float aa = a0*a0 + a1*a1 + a2*a2;
          float ab = a0*qa.z + a1*qa.w + a2;
          float at = a0*ta0 + a1*ta1 + a2*ta2;
          {
            float det = aa*bbv - ab*ab + 1e-9f;
            float n0 = -at*bbv + ab*bt;
            float n1 = aa*bt - ab*at;
            bool dpn = det >= 0.f;
            if (dpn ? (n0 > 0.f && n1 > 0.f) : (n0 < 0.f && n1 < 0.f)) scA0 += wa;
            if (dpn ? (n0 < 0.f && n1 < 0.f) : (n0 > 0.f && n1 > 0.f)) scA1 += wa;
          }
          {
            float ab2 = 2.0f*at*bt - ab;
            float det = aa*bbv - ab2*ab2 + 1e-9f;
            float n0 = -at*bbv + ab2*bt;
            float n1 = aa*bt - ab2*at;
            bool dpn = det >= 0.f;
            if (dpn ? (n0 > 0.f && n1 > 0.f) : (n0 < 0.f && n1 < 0.f)) scA2 += wa;
            if (dpn ? (n0 < 0.f && n1 < 0.f) : (n0 > 0.f && n1 > 0.f)) scA3 += wa;
          }
        }
        // batch B
        {
          float bbv = qb.z*qb.z + qb.w*qb.w + 1.0f;
          float bt = qb.z*tb0 + qb.w*tb1 + tb2;
          float a0 = RB[0]*qb.x + RB[1]*qb.y + RB[2];
          float a1 = RB[3]*qb.x + RB[4]*qb.y + RB[5];
          float a2 = RB[6]*qb.x + RB[7]*qb.y + RB[8];
          float aa = a0*a0 + a1*a1 + a2*a2;
          float ab = a0*qb.z + a1*qb.w + a2;
          float at = a0*tb0 + a1*tb1 + a2*tb2;
          {
            float det = aa*bbv - ab*ab + 1e-9f;
            float n0 = -at*bbv + ab*bt;
            float n1 = aa*bt - ab*at;
            bool dpn = det >= 0.f;
            if (dpn ? (n0 > 0.f && n1 > 0.f) : (n0 < 0.f && n1 < 0.f)) scB0 += wb;
            if (dpn ? (n0 < 0.f && n1 < 0.f) : (n0 > 0.f && n1 > 0.f)) scB1 += wb;
          }
          {
            float ab2 = 2.0f*at*bt - ab;
            float det = aa*bbv - ab2*ab2 + 1e-9f;
            float n0 = -at*bbv + ab2*bt;
            float n1 = aa*bt - ab2*at;
            bool dpn = det >= 0.f;
            if (dpn ? (n0 > 0.f && n1 > 0.f) : (n0 < 0.f && n1 < 0.f)) scB2 += wb;
            if (dpn ? (n0 < 0.f && n1 < 0.f) : (n0 > 0.f && n1 > 0.f)) scB3 += wb;
          }
        }
      }
    } else {
      // general path: recompute normalization from global per batch
      for (int s2 = 0; s2 < 2; s2++) {
        const float2* kp0 = s2 ? kp0B : kp0A;
        const float2* kp1 = s2 ? kp1B : kp1A;
        const float*  wv  = s2 ? wvB  : wvA;
        float Ki0[9], Ki1[9], Rl[9];
        #pragma unroll
        for (int i=0;i<9;i++){ Ki0[i]=sKi[s2][i]; Ki1[i]=sKi[s2][9+i]; Rl[i]=sR1[s2][i]; }
        float tv0=st3[s2][0], tv1=st3[s2][1], tv2=st3[s2][2];
        float c0=0.f,c1=0.f,c2=0.f,c3=0.f;
        #pragma unroll
        for (int k = 0; k < NPTS/256; k++) {
          int n = tid + k*256;
          float2 p0 = kp0[n]; float2 p1 = kp1[n]; float w = wv[n];
          float x00 = Ki0[0]*p0.x + Ki0[1]*p0.y + Ki0[2];
          float x01 = Ki0[3]*p0.x + Ki0[4]*p0.y + Ki0[5];
          float x02 = Ki0[6]*p0.x + Ki0[7]*p0.y + Ki0[8];
          float x10 = Ki1[0]*p1.x + Ki1[1]*p1.y + Ki1[2];
          float x11 = Ki1[3]*p1.x + Ki1[4]*p1.y + Ki1[5];
          float x12 = Ki1[6]*p1.x + Ki1[7]*p1.y + Ki1[8];
          float bbv = x10*x10 + x11*x11 + x12*x12;
          float bt = x10*tv0 + x11*tv1 + x12*tv2;
          float a0 = Rl[0]*x00 + Rl[1]*x01 + Rl[2]*x02;
          float a1 = Rl[3]*x00 + Rl[4]*x01 + Rl[5]*x02;
          float a2 = Rl[6]*x00 + Rl[7]*x01 + Rl[8]*x02;
          float aa = a0*a0 + a1*a1 + a2*a2;
          float ab = a0*x10 + a1*x11 + a2*x12;
          float at = a0*tv0 + a1*tv1 + a2*tv2;
          {
            float det = aa*bbv - ab*ab + 1e-9f;
            float n0 = -at*bbv + ab*bt;
            float n1 = aa*bt - ab*at;
            bool dpn = det >= 0.f;
            if (dpn ? (n0 > 0.f && n1 > 0.f) : (n0 < 0.f && n1 < 0.f)) c0 += w;
            if (dpn ? (n0 < 0.f && n1 < 0.f) : (n0 > 0.f && n1 > 0.f)) c1 += w;
          }
          {
            float ab2 = 2.0f*at*bt - ab;
            float det = aa*bbv - ab2*ab2 + 1e-9f;
            float n0 = -at*bbv + ab2*bt;
            float n1 = aa*bt - ab2*at;
            bool dpn = det >= 0.f;
            if (dpn ? (n0 > 0.f && n1 > 0.f) : (n0 < 0.f && n1 < 0.f)) c2 += w;
            if (dpn ? (n0 < 0.f && n1 < 0.f) : (n0 > 0.f && n1 > 0.f)) c3 += w;
          }
        }
        if (s2 == 0) { scA0=c0; scA1=c1; scA2=c2; scA3=c3; }
        else         { scB0=c0; scB1=c1; scB2=c2; scB3=c3; }
      }
    }
  }

  // ---- reductions + outputs, batch A then batch B ----
  for (int s = 0; s < 2; s++) {
    float sc0 = s ? scB0 : scA0;
    float sc1 = s ? scB1 : scA1;
    float sc2 = s ? scB2 : scA2;
    float sc3 = s ? scB3 : scA3;
    #pragma unroll
    for (int off=16; off; off>>=1) {
      sc0 += __shfl_down_sync(FULLM, sc0, off);
      sc1 += __shfl_down_sync(FULLM, sc1, off);
      sc2 += __shfl_down_sync(FULLM, sc2, off);
      sc3 += __shfl_down_sync(FULLM, sc3, off);
    }
    if (lane == 0) { sred[warp][0]=sc0; sred[warp][1]=sc1; sred[warp][2]=sc2; sred[warp][3]=sc3; }
    __syncthreads();
    if (tid == 0) {
      const int bb = blockIdx.x*2 + s;
      float s0=0.f, s1=0.f, s2v=0.f, s3=0.f;
      #pragma unroll
      for (int wp=0; wp<8; wp++){ s0+=sred[wp][0]; s1+=sred[wp][1]; s2v+=sred[wp][2]; s3+=sred[wp][3]; }
      float bs = s0; int bi = 0;
      if (s1 > bs){ bs=s1; bi=1; }
      if (s2v > bs){ bs=s2v; bi=2; }
      if (s3 > bs){ bs=s3; bi=3; }
      float Rsel[9];
      if (bi < 2) {
        #pragma unroll
        for (int i=0;i<9;i++) Rsel[i] = sR1[s][i];
      } else {
        float t3a[3] = {st3[s][0], st3[s][1], st3[s][2]};
        #pragma unroll
        for (int i=0;i<3;i++) {
          #pragma unroll
          for (int j=0;j<3;j++) {
            float dotc = t3a[0]*sR1[s][0*3+j] + t3a[1]*sR1[s][1*3+j] + t3a[2]*sR1[s][2*3+j];
            Rsel[i*3+j] = 2.0f*t3a[i]*dotc - sR1[s][i*3+j];
          }
        }
      }
      float sgn = (bi & 1) ? -1.f : 1.f;
      float ts = tscale[bb*2];
      float t0 = (sgn*st3[s][0])*ts;
      float t1 = (sgn*st3[s][1])*ts;
      float t2 = (sgn*st3[s][2])*ts;
      float* o = out + (size_t)bb*32;
      o[0]=Rsel[0]; o[1]=Rsel[1]; o[2]=Rsel[2];  o[3]=t0;
      o[4]=Rsel[3]; o[5]=Rsel[4]; o[6]=Rsel[5];  o[7]=t1;
      o[8]=Rsel[6]; o[9]=Rsel[7]; o[10]=Rsel[8]; o[11]=t2;
      o[12]=0.f; o[13]=0.f; o[14]=0.f; o[15]=1.f;
      float ti0 = -(Rsel[0]*t0 + Rsel[3]*t1 + Rsel[6]*t2);
      float ti1 = -(Rsel[1]*t0 + Rsel[4]*t1 + Rsel[7]*t2);
      float ti2 = -(Rsel[2]*t0 + Rsel[5]*t1 + Rsel[8]*t2);
      o[16]=Rsel[0]; o[17]=Rsel[3]; o[18]=Rsel[6]; o[19]=ti0;
      o[20]=Rsel[1]; o[21]=Rsel[4]; o[22]=Rsel[7]; o[23]=ti1;
      o[24]=Rsel[2]; o[25]=Rsel[5]; o[26]=Rsel[8]; o[27]=ti2;
      o[28]=0.f; o[29]=0.f; o[30]=0.f; o[31]=1.f;
    }
    __syncthreads();
  }
}

extern "C" void kernel_launch(void* const* d_in, const int* in_sizes, int n_in,
                              void* d_out, int out_size) {
  const float* kpts0  = (const float*)d_in[0];
  const float* kpts1  = (const float*)d_in[1];
  const float* conf   = (const float*)d_in[2];
  const float* tscale = (const float*)d_in[3];
  const float* Kmat   = (const float*)d_in[4];
  float* out = (float*)d_out;

  cudaFuncSetAttribute(k_fused, cudaFuncAttributeMaxDynamicSharedMemorySize, DYN_SMEM);
  k_fused<<<BATCH/2, 256, DYN_SMEM>>>(kpts0, kpts1, conf, tscale, Kmat, out);
}